// round 2
// baseline (speedup 1.0000x reference)
#include <cuda_runtime.h>
#include <math.h>

// Problem constants
#define Dm   512
#define Hn   8
#define DH   64
#define NBLK 6
#define Vv   32000
#define Ff   2048
#define Bb   2
#define Ll   1024
#define NTOK (Bb * Ll)   // 2048

// ---------------------------------------------------------------------------
// Scratch (device globals; no allocation allowed)
// ---------------------------------------------------------------------------
__device__ float g_h [NTOK * Dm];
__device__ float g_y [NTOK * Dm];
__device__ float g_q [NTOK * Dm];
__device__ float g_k [NTOK * Dm];
__device__ float g_v [NTOK * Dm];
__device__ float g_o [NTOK * Dm];
__device__ float g_ff[NTOK * Ff];

// ---------------------------------------------------------------------------
// Embedding * sqrt(D) + sinusoidal positional encoding
// grid = NTOK blocks, 128 threads, 4 dims/thread
// ---------------------------------------------------------------------------
__global__ void embed_kernel(const int* __restrict__ x,
                             const float* __restrict__ emb,
                             float* __restrict__ h) {
    int n = blockIdx.x;
    int l = n & (Ll - 1);
    int tok = x[n];
    int d0 = threadIdx.x * 4;
#pragma unroll
    for (int u = 0; u < 4; u++) {
        int d = d0 + u;
        int i = (d < 256) ? d : d - 256;
        float denom = powf(10000.0f, (float)i * (1.0f / 256.0f));
        float ang = (float)l / denom;
        float pos = (d < 256) ? sinf(ang) : cosf(ang);
        h[(size_t)n * Dm + d] = emb[(size_t)tok * Dm + d] * 22.62741699796952f + pos;
    }
}

// ---------------------------------------------------------------------------
// LayerNorm: one block per row (D=512), 128 threads, 4 floats/thread
// ---------------------------------------------------------------------------
__global__ void ln_kernel(const float* __restrict__ x,
                          const float* __restrict__ gw,
                          const float* __restrict__ bw,
                          float* __restrict__ y) {
    int row = blockIdx.x;
    int t = threadIdx.x;
    float4 xv = ((const float4*)(x + (size_t)row * Dm))[t];
    float s  = xv.x + xv.y + xv.z + xv.w;
    float ss = xv.x * xv.x + xv.y * xv.y + xv.z * xv.z + xv.w * xv.w;
#pragma unroll
    for (int o = 16; o > 0; o >>= 1) {
        s  += __shfl_xor_sync(0xFFFFFFFFu, s, o);
        ss += __shfl_xor_sync(0xFFFFFFFFu, ss, o);
    }
    __shared__ float sh_s[4], sh_ss[4];
    int w = t >> 5, lane = t & 31;
    if (lane == 0) { sh_s[w] = s; sh_ss[w] = ss; }
    __syncthreads();
    s  = sh_s[0] + sh_s[1] + sh_s[2] + sh_s[3];
    ss = sh_ss[0] + sh_ss[1] + sh_ss[2] + sh_ss[3];
    float mean = s * (1.0f / Dm);
    float var  = ss * (1.0f / Dm) - mean * mean;
    float inv = rsqrtf(var + 1e-6f);
    float4 gv = ((const float4*)gw)[t];
    float4 bv = ((const float4*)bw)[t];
    float4 ov;
    ov.x = (xv.x - mean) * inv * gv.x + bv.x;
    ov.y = (xv.y - mean) * inv * gv.y + bv.y;
    ov.z = (xv.z - mean) * inv * gv.z + bv.z;
    ov.w = (xv.w - mean) * inv * gv.w + bv.w;
    ((float4*)(y + (size_t)row * Dm))[t] = ov;
}

// ---------------------------------------------------------------------------
// SGEMM: C[M,N] = op(A[M,K] @ B) (+bias)(+relu)(+res)
// TB=false: B is [K,N] row-major. TB=true: B is [N,K] row-major (C = A @ B^T).
// BM=BN=128, BK=16, 256 threads, 8x8 microtile. Requires M%128==N%128==K%16==0.
// ---------------------------------------------------------------------------
template <bool TB, bool BIAS, bool RELU, bool RES>
__global__ void __launch_bounds__(256)
sgemm_kernel(const float* __restrict__ A, const float* __restrict__ B,
             const float* __restrict__ bias, const float* res,
             float* C, int M, int N, int K) {
    __shared__ float As[16][128];
    __shared__ float Bs[16][128];
    int tid = threadIdx.x;
    int tx = tid & 15, ty = tid >> 4;
    int m0 = blockIdx.y * 128, n0 = blockIdx.x * 128;
    float acc[8][8] = {};
    int lr = tid >> 2;            // 0..63
    int lc = (tid & 3) << 2;      // 0,4,8,12
    int br = tid >> 5;            // 0..7
    int bc = (tid & 31) << 2;     // 0..124

    for (int k0 = 0; k0 < K; k0 += 16) {
#pragma unroll
        for (int p = 0; p < 2; p++) {
            int r = lr + p * 64;
            float4 va = *(const float4*)(A + (size_t)(m0 + r) * K + k0 + lc);
            As[lc + 0][r] = va.x; As[lc + 1][r] = va.y;
            As[lc + 2][r] = va.z; As[lc + 3][r] = va.w;
        }
        if (TB) {
#pragma unroll
            for (int p = 0; p < 2; p++) {
                int r = lr + p * 64;
                float4 vb = *(const float4*)(B + (size_t)(n0 + r) * K + k0 + lc);
                Bs[lc + 0][r] = vb.x; Bs[lc + 1][r] = vb.y;
                Bs[lc + 2][r] = vb.z; Bs[lc + 3][r] = vb.w;
            }
        } else {
#pragma unroll
            for (int p = 0; p < 2; p++) {
                int r = br + p * 8;
                *(float4*)&Bs[r][bc] = *(const float4*)(B + (size_t)(k0 + r) * N + n0 + bc);
            }
        }
        __syncthreads();
#pragma unroll
        for (int kk = 0; kk < 16; kk++) {
            float a[8], bf[8];
            *(float4*)&a[0]  = *(const float4*)&As[kk][ty * 8];
            *(float4*)&a[4]  = *(const float4*)&As[kk][ty * 8 + 4];
            *(float4*)&bf[0] = *(const float4*)&Bs[kk][tx * 8];
            *(float4*)&bf[4] = *(const float4*)&Bs[kk][tx * 8 + 4];
#pragma unroll
            for (int i = 0; i < 8; i++)
#pragma unroll
                for (int j = 0; j < 8; j++)
                    acc[i][j] += a[i] * bf[j];
        }
        __syncthreads();
    }
#pragma unroll
    for (int i = 0; i < 8; i++) {
        int mrow = m0 + ty * 8 + i;
#pragma unroll
        for (int j = 0; j < 8; j += 4) {
            int ncol = n0 + tx * 8 + j;
            float4 vv = *(float4*)&acc[i][j];
            if (BIAS) {
                float4 bb = *(const float4*)(bias + ncol);
                vv.x += bb.x; vv.y += bb.y; vv.z += bb.z; vv.w += bb.w;
            }
            if (RELU) {
                vv.x = fmaxf(vv.x, 0.f); vv.y = fmaxf(vv.y, 0.f);
                vv.z = fmaxf(vv.z, 0.f); vv.w = fmaxf(vv.w, 0.f);
            }
            if (RES) {
                float4 rr = *(const float4*)(res + (size_t)mrow * N + ncol);
                vv.x += rr.x; vv.y += rr.y; vv.z += rr.z; vv.w += rr.w;
            }
            *(float4*)(C + (size_t)mrow * N + ncol) = vv;
        }
    }
}

template <bool TB, bool BIAS, bool RELU, bool RES>
static inline void gemm(const float* A, const float* B, const float* bias,
                        const float* res, float* C, int M, int N, int K) {
    dim3 grid(N / 128, M / 128);
    sgemm_kernel<TB, BIAS, RELU, RES><<<grid, 256>>>(A, B, bias, res, C, M, N, K);
}

// ---------------------------------------------------------------------------
// Fused attention (flash-style, online softmax).
// Layout for Q/K/V/O: [B*L, D] with D = H*64 head-interleaved (= concat heads).
// grid = (L/128, H, B), 128 threads, one query row per thread.
// Causal masking via loop bounds == additive -1e10 bias (exp underflows to 0).
// ---------------------------------------------------------------------------
template <bool CAUSAL>
__global__ void __launch_bounds__(128)
attn_kernel(const float* __restrict__ Q, const float* __restrict__ K,
            const float* __restrict__ V, float* __restrict__ O) {
    __shared__ float Ks[64][64];
    __shared__ float Vs[64][64];
    int t = threadIdx.x;
    int qt = blockIdx.x, hh = blockIdx.y, b = blockIdx.z;
    int q = qt * 128 + t;
    const float* qptr = Q + ((size_t)(b * Ll + q)) * Dm + hh * DH;
    float4 qv[16];
#pragma unroll
    for (int d = 0; d < 16; d++) qv[d] = ((const float4*)qptr)[d];
    float4 ov[16];
#pragma unroll
    for (int d = 0; d < 16; d++) ov[d] = make_float4(0.f, 0.f, 0.f, 0.f);
    float m = -1e30f, lsum = 0.f;

    int kmax = CAUSAL ? (qt * 128 + 128) : Ll;
    for (int k0 = 0; k0 < kmax; k0 += 64) {
#pragma unroll
        for (int it = 0; it < 8; it++) {
            int idx = t + it * 128;      // 0..1023 float4 slots
            int r = idx >> 4;            // 0..63
            int c = (idx & 15) << 2;     // 0..60
            size_t off = ((size_t)(b * Ll + k0 + r)) * Dm + hh * DH + c;
            *(float4*)&Ks[r][c] = *(const float4*)(K + off);
            *(float4*)&Vs[r][c] = *(const float4*)(V + off);
        }
        __syncthreads();
        int jend = 64;
        if (CAUSAL) {
            int lim = q - k0 + 1;
            jend = lim < 64 ? (lim < 0 ? 0 : lim) : 64;
        }
        for (int j = 0; j < jend; j++) {
            const float4* kr = (const float4*)Ks[j];
            float s = 0.f;
#pragma unroll
            for (int d = 0; d < 16; d++) {
                float4 kv = kr[d];
                s += qv[d].x * kv.x + qv[d].y * kv.y + qv[d].z * kv.z + qv[d].w * kv.w;
            }
            s *= 0.125f;   // 1/sqrt(64)
            float mn = fmaxf(m, s);
            float c = __expf(m - mn);
            float p = __expf(s - mn);
            m = mn;
            lsum = lsum * c + p;
            const float4* vr = (const float4*)Vs[j];
#pragma unroll
            for (int d = 0; d < 16; d++) {
                float4 vvv = vr[d];
                ov[d].x = ov[d].x * c + p * vvv.x;
                ov[d].y = ov[d].y * c + p * vvv.y;
                ov[d].z = ov[d].z * c + p * vvv.z;
                ov[d].w = ov[d].w * c + p * vvv.w;
            }
        }
        __syncthreads();
    }
    float inv = 1.0f / lsum;
    float* optr = O + ((size_t)(b * Ll + q)) * Dm + hh * DH;
#pragma unroll
    for (int d = 0; d < 16; d++) {
        float4 r = ov[d];
        r.x *= inv; r.y *= inv; r.z *= inv; r.w *= inv;
        ((float4*)optr)[d] = r;
    }
}

// ---------------------------------------------------------------------------
// kernel_launch
// ---------------------------------------------------------------------------
extern "C" void kernel_launch(void* const* d_in, const int* in_sizes, int n_in,
                              void* d_out, int out_size) {
    const int*   x     = (const int*)  d_in[0];
    const float* ctx   = (const float*)d_in[1];
    const float* emb   = (const float*)d_in[2];
    const float* wq_s  = (const float*)d_in[3];
    const float* wk_s  = (const float*)d_in[4];
    const float* wv_s  = (const float*)d_in[5];
    const float* wo_s  = (const float*)d_in[6];
    const float* wq_c  = (const float*)d_in[7];
    const float* wk_c  = (const float*)d_in[8];
    const float* wv_c  = (const float*)d_in[9];
    const float* wo_c  = (const float*)d_in[10];
    const float* w1    = (const float*)d_in[11];
    const float* b1    = (const float*)d_in[12];
    const float* w2    = (const float*)d_in[13];
    const float* b2    = (const float*)d_in[14];
    const float* ln1_g = (const float*)d_in[15];
    const float* ln1_b = (const float*)d_in[16];
    const float* ln2_g = (const float*)d_in[17];
    const float* ln2_b = (const float*)d_in[18];
    const float* ln3_g = (const float*)d_in[19];
    const float* ln3_b = (const float*)d_in[20];
    const float* lnf_g = (const float*)d_in[21];
    const float* lnf_b = (const float*)d_in[22];
    float* out = (float*)d_out;

    float *h, *y, *q, *k, *v, *o, *ff;
    cudaGetSymbolAddress((void**)&h,  g_h);
    cudaGetSymbolAddress((void**)&y,  g_y);
    cudaGetSymbolAddress((void**)&q,  g_q);
    cudaGetSymbolAddress((void**)&k,  g_k);
    cudaGetSymbolAddress((void**)&v,  g_v);
    cudaGetSymbolAddress((void**)&o,  g_o);
    cudaGetSymbolAddress((void**)&ff, g_ff);

    embed_kernel<<<NTOK, 128>>>(x, emb, h);

    const size_t DD = (size_t)Dm * Dm;
    const size_t DF = (size_t)Dm * Ff;
    dim3 agrid(Ll / 128, Hn, Bb);

    for (int i = 0; i < NBLK; i++) {
        // --- self attention ---
        ln_kernel<<<NTOK, 128>>>(h, ln1_g + i * Dm, ln1_b + i * Dm, y);
        gemm<false, false, false, false>(y, wq_s + i * DD, nullptr, nullptr, q, NTOK, Dm, Dm);
        gemm<false, false, false, false>(y, wk_s + i * DD, nullptr, nullptr, k, NTOK, Dm, Dm);
        gemm<false, false, false, false>(y, wv_s + i * DD, nullptr, nullptr, v, NTOK, Dm, Dm);
        attn_kernel<true><<<agrid, 128>>>(q, k, v, o);
        gemm<false, false, false, true>(o, wo_s + i * DD, nullptr, h, h, NTOK, Dm, Dm);

        // --- cross attention ---
        ln_kernel<<<NTOK, 128>>>(h, ln2_g + i * Dm, ln2_b + i * Dm, y);
        gemm<false, false, false, false>(y,   wq_c + i * DD, nullptr, nullptr, q, NTOK, Dm, Dm);
        gemm<false, false, false, false>(ctx, wk_c + i * DD, nullptr, nullptr, k, NTOK, Dm, Dm);
        gemm<false, false, false, false>(ctx, wv_c + i * DD, nullptr, nullptr, v, NTOK, Dm, Dm);
        attn_kernel<false><<<agrid, 128>>>(q, k, v, o);
        gemm<false, false, false, true>(o, wo_c + i * DD, nullptr, h, h, NTOK, Dm, Dm);

        // --- FFN ---
        ln_kernel<<<NTOK, 128>>>(h, ln3_g + i * Dm, ln3_b + i * Dm, y);
        gemm<false, true, true, false>(y, w1 + i * DF, b1 + (size_t)i * Ff, nullptr, ff, NTOK, Ff, Dm);
        gemm<false, true, false, true>(ff, w2 + i * DF, b2 + (size_t)i * Dm, h, h, NTOK, Dm, Ff);
    }

    // --- final LN + logits = y @ emb^T ---
    ln_kernel<<<NTOK, 128>>>(h, lnf_g, lnf_b, y);
    gemm<true, false, false, false>(y, emb, nullptr, nullptr, out, NTOK, Vv, Dm);
}

// round 7
// speedup vs baseline: 1.6238x; 1.6238x over previous
#include <cuda_runtime.h>
#include <cstdint>
#include <math.h>

// Problem constants
#define Dm   512
#define Hn   8
#define DH   64
#define NBLK 6
#define Vv   32000
#define Ff   2048
#define Bb   2
#define Ll   1024
#define NTOK (Bb * Ll)   // 2048

// ---------------------------------------------------------------------------
// Scratch (device globals; no allocation allowed)
// ---------------------------------------------------------------------------
__device__ float g_h [NTOK * Dm];
__device__ float g_y [NTOK * Dm];
__device__ float g_q [NTOK * Dm];
__device__ float g_k [NTOK * Dm];
__device__ float g_v [NTOK * Dm];
__device__ float g_o [NTOK * Dm];
__device__ float g_ff[NTOK * Ff];

// Transposed weights: per block: 8 x [512x512] + w1T [2048x512] + w2T [512x2048]
#define WBLK_STRIDE 4194304ull          // 8*262144 + 1048576 + 1048576
#define W1T_OFF     2097152ull
#define W2T_OFF     3145728ull
__device__ float g_wt[NBLK * WBLK_STRIDE];

// ---------------------------------------------------------------------------
// tf32 helpers (portable PTX only: sm_80+ baseline ISA, valid on compute_103)
// ---------------------------------------------------------------------------
__device__ __forceinline__ uint32_t f2tf(float f) {
    uint32_t u;
    asm("cvt.rna.tf32.f32 %0, %1;" : "=r"(u) : "f"(f));
    return u;
}

__device__ __forceinline__ void mma_tf32(float c[4], const uint32_t a[4],
                                         const uint32_t b[2]) {
    asm volatile(
        "mma.sync.aligned.m16n8k8.row.col.f32.tf32.tf32.f32 "
        "{%0,%1,%2,%3}, {%4,%5,%6,%7}, {%8,%9}, {%0,%1,%2,%3};"
        : "+f"(c[0]), "+f"(c[1]), "+f"(c[2]), "+f"(c[3])
        : "r"(a[0]), "r"(a[1]), "r"(a[2]), "r"(a[3]),
          "r"(b[0]), "r"(b[1]));
}

// ---------------------------------------------------------------------------
// TF32 tensor-core GEMM: C[M,N] = A[M,K] @ BT[N,K]^T  (+bias)(+relu)(+res)
// CTA 128x128, BK=32, 256 threads = 4(m) x 2(n) warps, warp tile 32x64.
// Requires M%128==0, N%128==0, K%32==0.
// Smem row stride 36 words -> conflict-free fragment loads.
// ---------------------------------------------------------------------------
#define BKC 32
#define SSTR 36   // smem row stride in words

template <bool BIAS, bool RELU, bool RES>
__global__ void __launch_bounds__(256, 2)
mm_gemm(const float* __restrict__ A, const float* __restrict__ BT,
        const float* __restrict__ bias, const float* __restrict__ res,
        float* __restrict__ C, int M, int N, int K) {
    __shared__ uint32_t As[128 * SSTR];
    __shared__ uint32_t Bs[128 * SSTR];

    int tid = threadIdx.x;
    int w = tid >> 5, lane = tid & 31;
    int g = lane >> 2, t4 = lane & 3;
    int wm = w >> 1, wn = w & 1;           // warp grid 4x2
    int n0 = blockIdx.x * 128, m0 = blockIdx.y * 128;

    float acc[2][8][4];
#pragma unroll
    for (int mt = 0; mt < 2; mt++)
#pragma unroll
        for (int nt = 0; nt < 8; nt++)
#pragma unroll
            for (int i = 0; i < 4; i++) acc[mt][nt][i] = 0.f;

    // staging: 2 threads per row; parity 0 -> float4 cols 0..3, parity 1 -> 4..7
    int lrow = tid >> 1;                   // 0..127
    int base = (tid & 1) * 4;              // float4 col offset

    for (int k0 = 0; k0 < K; k0 += BKC) {
        const float* Ap = A  + (size_t)(m0 + lrow) * K + k0;
        const float* Bp = BT + (size_t)(n0 + lrow) * K + k0;
        uint32_t* Ad = As + lrow * SSTR;
        uint32_t* Bd = Bs + lrow * SSTR;
#pragma unroll
        for (int c4 = 0; c4 < 4; c4++) {
            float4 va = *(const float4*)(Ap + ((base + c4) << 2));
            *(uint4*)(Ad + ((base + c4) << 2)) =
                make_uint4(f2tf(va.x), f2tf(va.y), f2tf(va.z), f2tf(va.w));
            float4 vb = *(const float4*)(Bp + ((base + c4) << 2));
            *(uint4*)(Bd + ((base + c4) << 2)) =
                make_uint4(f2tf(vb.x), f2tf(vb.y), f2tf(vb.z), f2tf(vb.w));
        }
        __syncthreads();

#pragma unroll
        for (int k8 = 0; k8 < BKC / 8; k8++) {
            int kk = (k8 << 3) + t4;
            uint32_t af[2][4];
#pragma unroll
            for (int mt = 0; mt < 2; mt++) {
                int m = wm * 32 + mt * 16 + g;
                const uint32_t* ap = As + m * SSTR + kk;
                af[mt][0] = ap[0];
                af[mt][1] = ap[8 * SSTR];
                af[mt][2] = ap[4];
                af[mt][3] = ap[8 * SSTR + 4];
            }
            uint32_t bf[8][2];
#pragma unroll
            for (int nt = 0; nt < 8; nt++) {
                int n = wn * 64 + nt * 8 + g;
                const uint32_t* bp = Bs + n * SSTR + kk;
                bf[nt][0] = bp[0];
                bf[nt][1] = bp[4];
            }
#pragma unroll
            for (int mt = 0; mt < 2; mt++)
#pragma unroll
                for (int nt = 0; nt < 8; nt++)
                    mma_tf32(acc[mt][nt], af[mt], bf[nt]);
        }
        __syncthreads();
    }

    // epilogue: c0,c1 -> (row, col,col+1); c2,c3 -> (row+8, col,col+1)
#pragma unroll
    for (int mt = 0; mt < 2; mt++) {
        int r0 = m0 + wm * 32 + mt * 16 + g;
#pragma unroll
        for (int nt = 0; nt < 8; nt++) {
            int cc = n0 + wn * 64 + nt * 8 + t4 * 2;
            float2 v0 = make_float2(acc[mt][nt][0], acc[mt][nt][1]);
            float2 v1 = make_float2(acc[mt][nt][2], acc[mt][nt][3]);
            if (BIAS) {
                float2 bb = *(const float2*)(bias + cc);
                v0.x += bb.x; v0.y += bb.y; v1.x += bb.x; v1.y += bb.y;
            }
            if (RELU) {
                v0.x = fmaxf(v0.x, 0.f); v0.y = fmaxf(v0.y, 0.f);
                v1.x = fmaxf(v1.x, 0.f); v1.y = fmaxf(v1.y, 0.f);
            }
            if (RES) {
                float2 r4 = *(const float2*)(res + (size_t)r0 * N + cc);
                v0.x += r4.x; v0.y += r4.y;
                float2 r5 = *(const float2*)(res + (size_t)(r0 + 8) * N + cc);
                v1.x += r5.x; v1.y += r5.y;
            }
            *(float2*)(C + (size_t)r0 * N + cc) = v0;
            *(float2*)(C + (size_t)(r0 + 8) * N + cc) = v1;
        }
    }
}

template <bool BIAS, bool RELU, bool RES>
static inline void tgemm(const float* A, const float* BT, const float* bias,
                         const float* res, float* C, int M, int N, int K) {
    dim3 grid(N / 128, M / 128);
    mm_gemm<BIAS, RELU, RES><<<grid, 256>>>(A, BT, bias, res, C, M, N, K);
}

// ---------------------------------------------------------------------------
// Weight transpose: [K,N] row-major -> [N,K] row-major
// ---------------------------------------------------------------------------
struct P8 { const float* p[8]; };

__global__ void trans_dd(P8 s, float* dst) {
    __shared__ float t[32][33];
    int z = blockIdx.z;
    int kd = z / 6, i = z - kd * 6;
    const float* src = s.p[kd] + (size_t)i * 262144;
    float* d = dst + (size_t)i * WBLK_STRIDE + (size_t)kd * 262144;
    int tx = threadIdx.x, ty = threadIdx.y;
    int x = blockIdx.x * 32 + tx;
    int y0 = blockIdx.y * 32;
#pragma unroll
    for (int r = 0; r < 32; r += 8)
        t[ty + r][tx] = src[(size_t)(y0 + ty + r) * 512 + x];
    __syncthreads();
    int x2 = y0 + tx;
    int y2 = blockIdx.x * 32;
#pragma unroll
    for (int r = 0; r < 32; r += 8)
        d[(size_t)(y2 + ty + r) * 512 + x2] = t[tx][ty + r];
}

__global__ void trans_rc(const float* __restrict__ src, float* __restrict__ dst,
                         int R, int C, size_t dOff) {
    __shared__ float t[32][33];
    const float* s = src + (size_t)blockIdx.z * R * C;
    float* d = dst + (size_t)blockIdx.z * WBLK_STRIDE + dOff;
    int tx = threadIdx.x, ty = threadIdx.y;
    int x = blockIdx.x * 32 + tx;
    int y0 = blockIdx.y * 32;
#pragma unroll
    for (int r = 0; r < 32; r += 8)
        t[ty + r][tx] = s[(size_t)(y0 + ty + r) * C + x];
    __syncthreads();
    int x2 = y0 + tx;
    int y2 = blockIdx.x * 32;
#pragma unroll
    for (int r = 0; r < 32; r += 8)
        d[(size_t)(y2 + ty + r) * R + x2] = t[tx][ty + r];
}

// ---------------------------------------------------------------------------
// Embedding * sqrt(D) + sinusoidal positional encoding
// ---------------------------------------------------------------------------
__global__ void embed_kernel(const int* __restrict__ x,
                             const float* __restrict__ emb,
                             float* __restrict__ h) {
    int n = blockIdx.x;
    int l = n & (Ll - 1);
    int tok = x[n];
    int d0 = threadIdx.x * 4;
#pragma unroll
    for (int u = 0; u < 4; u++) {
        int d = d0 + u;
        int i = (d < 256) ? d : d - 256;
        float denom = powf(10000.0f, (float)i * (1.0f / 256.0f));
        float ang = (float)l / denom;
        float pos = (d < 256) ? sinf(ang) : cosf(ang);
        h[(size_t)n * Dm + d] = emb[(size_t)tok * Dm + d] * 22.62741699796952f + pos;
    }
}

// ---------------------------------------------------------------------------
// LayerNorm: one block per row (D=512), 128 threads
// ---------------------------------------------------------------------------
__global__ void ln_kernel(const float* __restrict__ x,
                          const float* __restrict__ gw,
                          const float* __restrict__ bw,
                          float* __restrict__ y) {
    int row = blockIdx.x;
    int t = threadIdx.x;
    float4 xv = ((const float4*)(x + (size_t)row * Dm))[t];
    float s  = xv.x + xv.y + xv.z + xv.w;
    float ss = xv.x * xv.x + xv.y * xv.y + xv.z * xv.z + xv.w * xv.w;
#pragma unroll
    for (int o = 16; o > 0; o >>= 1) {
        s  += __shfl_xor_sync(0xFFFFFFFFu, s, o);
        ss += __shfl_xor_sync(0xFFFFFFFFu, ss, o);
    }
    __shared__ float sh_s[4], sh_ss[4];
    int w = t >> 5, lane = t & 31;
    if (lane == 0) { sh_s[w] = s; sh_ss[w] = ss; }
    __syncthreads();
    s  = sh_s[0] + sh_s[1] + sh_s[2] + sh_s[3];
    ss = sh_ss[0] + sh_ss[1] + sh_ss[2] + sh_ss[3];
    float mean = s * (1.0f / Dm);
    float var  = ss * (1.0f / Dm) - mean * mean;
    float inv = rsqrtf(var + 1e-6f);
    float4 gv = ((const float4*)gw)[t];
    float4 bv = ((const float4*)bw)[t];
    float4 ov;
    ov.x = (xv.x - mean) * inv * gv.x + bv.x;
    ov.y = (xv.y - mean) * inv * gv.y + bv.y;
    ov.z = (xv.z - mean) * inv * gv.z + bv.z;
    ov.w = (xv.w - mean) * inv * gv.w + bv.w;
    ((float4*)(y + (size_t)row * Dm))[t] = ov;
}

// ---------------------------------------------------------------------------
// Fused flash-style attention (fp32)
// ---------------------------------------------------------------------------
template <bool CAUSAL>
__global__ void __launch_bounds__(128)
attn_kernel(const float* __restrict__ Q, const float* __restrict__ K,
            const float* __restrict__ V, float* __restrict__ O) {
    __shared__ float Ks[64][64];
    __shared__ float Vs[64][64];
    int t = threadIdx.x;
    int qt = blockIdx.x, hh = blockIdx.y, b = blockIdx.z;
    int q = qt * 128 + t;
    const float* qptr = Q + ((size_t)(b * Ll + q)) * Dm + hh * DH;
    float4 qv[16];
#pragma unroll
    for (int d = 0; d < 16; d++) qv[d] = ((const float4*)qptr)[d];
    float4 ov[16];
#pragma unroll
    for (int d = 0; d < 16; d++) ov[d] = make_float4(0.f, 0.f, 0.f, 0.f);
    float m = -1e30f, lsum = 0.f;

    int kmax = CAUSAL ? (qt * 128 + 128) : Ll;
    for (int k0 = 0; k0 < kmax; k0 += 64) {
#pragma unroll
        for (int it = 0; it < 8; it++) {
            int idx = t + it * 128;
            int r = idx >> 4;
            int c = (idx & 15) << 2;
            size_t off = ((size_t)(b * Ll + k0 + r)) * Dm + hh * DH + c;
            *(float4*)&Ks[r][c] = *(const float4*)(K + off);
            *(float4*)&Vs[r][c] = *(const float4*)(V + off);
        }
        __syncthreads();
        int jend = 64;
        if (CAUSAL) {
            int lim = q - k0 + 1;
            jend = lim < 64 ? (lim < 0 ? 0 : lim) : 64;
        }
        for (int j = 0; j < jend; j++) {
            const float4* kr = (const float4*)Ks[j];
            float s = 0.f;
#pragma unroll
            for (int d = 0; d < 16; d++) {
                float4 kv = kr[d];
                s += qv[d].x * kv.x + qv[d].y * kv.y + qv[d].z * kv.z + qv[d].w * kv.w;
            }
            s *= 0.125f;
            float mn = fmaxf(m, s);
            float c = __expf(m - mn);
            float p = __expf(s - mn);
            m = mn;
            lsum = lsum * c + p;
            const float4* vr = (const float4*)Vs[j];
#pragma unroll
            for (int d = 0; d < 16; d++) {
                float4 vvv = vr[d];
                ov[d].x = ov[d].x * c + p * vvv.x;
                ov[d].y = ov[d].y * c + p * vvv.y;
                ov[d].z = ov[d].z * c + p * vvv.z;
                ov[d].w = ov[d].w * c + p * vvv.w;
            }
        }
        __syncthreads();
    }
    float inv = 1.0f / lsum;
    float* optr = O + ((size_t)(b * Ll + q)) * Dm + hh * DH;
#pragma unroll
    for (int d = 0; d < 16; d++) {
        float4 r = ov[d];
        r.x *= inv; r.y *= inv; r.z *= inv; r.w *= inv;
        ((float4*)optr)[d] = r;
    }
}

// ---------------------------------------------------------------------------
// kernel_launch
// ---------------------------------------------------------------------------
extern "C" void kernel_launch(void* const* d_in, const int* in_sizes, int n_in,
                              void* d_out, int out_size) {
    const int*   x     = (const int*)  d_in[0];
    const float* ctx   = (const float*)d_in[1];
    const float* emb   = (const float*)d_in[2];
    const float* wq_s  = (const float*)d_in[3];
    const float* wk_s  = (const float*)d_in[4];
    const float* wv_s  = (const float*)d_in[5];
    const float* wo_s  = (const float*)d_in[6];
    const float* wq_c  = (const float*)d_in[7];
    const float* wk_c  = (const float*)d_in[8];
    const float* wv_c  = (const float*)d_in[9];
    const float* wo_c  = (const float*)d_in[10];
    const float* w1    = (const float*)d_in[11];
    const float* b1    = (const float*)d_in[12];
    const float* w2    = (const float*)d_in[13];
    const float* b2    = (const float*)d_in[14];
    const float* ln1_g = (const float*)d_in[15];
    const float* ln1_b = (const float*)d_in[16];
    const float* ln2_g = (const float*)d_in[17];
    const float* ln2_b = (const float*)d_in[18];
    const float* ln3_g = (const float*)d_in[19];
    const float* ln3_b = (const float*)d_in[20];
    const float* lnf_g = (const float*)d_in[21];
    const float* lnf_b = (const float*)d_in[22];
    float* out = (float*)d_out;

    float *h, *y, *q, *k, *v, *o, *ff, *wt;
    cudaGetSymbolAddress((void**)&h,  g_h);
    cudaGetSymbolAddress((void**)&y,  g_y);
    cudaGetSymbolAddress((void**)&q,  g_q);
    cudaGetSymbolAddress((void**)&k,  g_k);
    cudaGetSymbolAddress((void**)&v,  g_v);
    cudaGetSymbolAddress((void**)&o,  g_o);
    cudaGetSymbolAddress((void**)&ff, g_ff);
    cudaGetSymbolAddress((void**)&wt, g_wt);

    // ---- transpose all weights into [N][K] scratch ----
    P8 p8;
    p8.p[0] = wq_s; p8.p[1] = wk_s; p8.p[2] = wv_s; p8.p[3] = wo_s;
    p8.p[4] = wq_c; p8.p[5] = wk_c; p8.p[6] = wv_c; p8.p[7] = wo_c;
    trans_dd<<<dim3(16, 16, 48), dim3(32, 8)>>>(p8, wt);
    trans_rc<<<dim3(64, 16, 6), dim3(32, 8)>>>(w1, wt, 512, 2048, W1T_OFF);
    trans_rc<<<dim3(16, 64, 6), dim3(32, 8)>>>(w2, wt, 2048, 512, W2T_OFF);

    embed_kernel<<<NTOK, 128>>>(x, emb, h);

    dim3 agrid(Ll / 128, Hn, Bb);

    for (int i = 0; i < NBLK; i++) {
        const float* WT = wt + (size_t)i * WBLK_STRIDE;
        // --- self attention ---
        ln_kernel<<<NTOK, 128>>>(h, ln1_g + i * Dm, ln1_b + i * Dm, y);
        tgemm<false, false, false>(y, WT + 0 * 262144ull, nullptr, nullptr, q, NTOK, Dm, Dm);
        tgemm<false, false, false>(y, WT + 1 * 262144ull, nullptr, nullptr, k, NTOK, Dm, Dm);
        tgemm<false, false, false>(y, WT + 2 * 262144ull, nullptr, nullptr, v, NTOK, Dm, Dm);
        attn_kernel<true><<<agrid, 128>>>(q, k, v, o);
        tgemm<false, false, true>(o, WT + 3 * 262144ull, nullptr, h, h, NTOK, Dm, Dm);

        // --- cross attention ---
        ln_kernel<<<NTOK, 128>>>(h, ln2_g + i * Dm, ln2_b + i * Dm, y);
        tgemm<false, false, false>(y,   WT + 4 * 262144ull, nullptr, nullptr, q, NTOK, Dm, Dm);
        tgemm<false, false, false>(ctx, WT + 5 * 262144ull, nullptr, nullptr, k, NTOK, Dm, Dm);
        tgemm<false, false, false>(ctx, WT + 6 * 262144ull, nullptr, nullptr, v, NTOK, Dm, Dm);
        attn_kernel<false><<<agrid, 128>>>(q, k, v, o);
        tgemm<false, false, true>(o, WT + 7 * 262144ull, nullptr, h, h, NTOK, Dm, Dm);

        // --- FFN ---
        ln_kernel<<<NTOK, 128>>>(h, ln3_g + i * Dm, ln3_b + i * Dm, y);
        tgemm<true, true, false>(y,  WT + W1T_OFF, b1 + (size_t)i * Ff, nullptr, ff, NTOK, Ff, Dm);
        tgemm<true, false, true>(ff, WT + W2T_OFF, b2 + (size_t)i * Dm, h, h, NTOK, Dm, Ff);
    }

    // --- final LN + logits = y @ emb^T (emb already [V][K]) ---
    ln_kernel<<<NTOK, 128>>>(h, lnf_g, lnf_b, y);
    tgemm<false, false, false>(y, emb, nullptr, nullptr, out, NTOK, Vv, Dm);
}

// round 9
// speedup vs baseline: 2.0145x; 1.2406x over previous
#include <cuda_runtime.h>
#include <cstdint>
#include <math.h>

// Problem constants
#define Dm   512
#define Hn   8
#define DH   64
#define NBLK 6
#define Vv   32000
#define Ff   2048
#define Bb   2
#define Ll   1024
#define NTOK (Bb * Ll)   // 2048

// ---------------------------------------------------------------------------
// Scratch (device globals; no allocation allowed)
// ---------------------------------------------------------------------------
__device__ float g_h [NTOK * Dm];
__device__ float g_y [NTOK * Dm];
__device__ float g_q [NTOK * Dm];
__device__ float g_k [NTOK * Dm];
__device__ float g_v [NTOK * Dm];
__device__ float g_o [NTOK * Dm];
__device__ float g_ff[NTOK * Ff];

// Transposed weights: per block: 8 x [512x512] + w1T [2048x512] + w2T [512x2048]
#define WBLK_STRIDE 4194304ull          // 8*262144 + 1048576 + 1048576
#define W1T_OFF     2097152ull
#define W2T_OFF     3145728ull
__device__ float g_wt[NBLK * WBLK_STRIDE];

// ---------------------------------------------------------------------------
// Portable PTX helpers (all sm_80+ baseline ISA, valid on compute_103)
// ---------------------------------------------------------------------------
__device__ __forceinline__ uint32_t s2u(const void* p) {
    uint32_t a;
    asm("{ .reg .u64 t; cvta.to.shared.u64 t, %1; cvt.u32.u64 %0, t; }"
        : "=r"(a) : "l"(p));
    return a;
}

__device__ __forceinline__ uint32_t f2tf(float f) {
    uint32_t u;
    asm("cvt.rna.tf32.f32 %0, %1;" : "=r"(u) : "f"(f));
    return u;
}

__device__ __forceinline__ void cpa16(uint32_t dst, const void* src) {
    asm volatile("cp.async.cg.shared.global [%0], [%1], 16;"
                 :: "r"(dst), "l"(src));
}

#define CP_COMMIT() asm volatile("cp.async.commit_group;")
#define CP_WAIT1()  asm volatile("cp.async.wait_group 1;")

__device__ __forceinline__ void mma_tf32(float c[4], const uint32_t a[4],
                                         const uint32_t b[2]) {
    asm volatile(
        "mma.sync.aligned.m16n8k8.row.col.f32.tf32.tf32.f32 "
        "{%0,%1,%2,%3}, {%4,%5,%6,%7}, {%8,%9}, {%0,%1,%2,%3};"
        : "+f"(c[0]), "+f"(c[1]), "+f"(c[2]), "+f"(c[3])
        : "r"(a[0]), "r"(a[1]), "r"(a[2]), "r"(a[3]),
          "r"(b[0]), "r"(b[1]));
}

// ---------------------------------------------------------------------------
// TF32 tensor-core GEMM: C[M,N] = A[M,K] @ BT[N,K]^T  (+bias)(+relu)(+res)
// CTA tile BMx128, BK=32, 256 threads, cp.async double-buffered.
//   BM=128: warp grid 4(m)x2(n), warp tile 32x64
//   BM=64 : warp grid 2(m)x4(n), warp tile 32x32  (for N=512 GEMMs: 2x CTAs)
// Requires M%BM==0, N%128==0, K%32==0, K>=64.
// Smem row stride 36 words -> fragment bank (4g+t4)%32, conflict-free.
// ---------------------------------------------------------------------------
#define BKC 32
#define SSTR 36   // smem row stride in words

template <int BM, bool BIAS, bool RELU, bool RES>
__global__ void __launch_bounds__(256, 2)
mm_gemm(const float* __restrict__ A, const float* __restrict__ BT,
        const float* __restrict__ bias, const float* __restrict__ res,
        float* __restrict__ C, int M, int N, int K) {
    constexpr int WGN = (BM == 128) ? 2 : 4;      // warps along n
    constexpr int NT  = (BM == 128) ? 8 : 4;      // 8-col n-tiles per warp
    constexpr int AW  = BM * SSTR;                // words per A buffer
    constexpr int BW  = 128 * SSTR;               // words per B buffer
    extern __shared__ uint32_t smem[];
    uint32_t sbase = s2u(smem);

    int tid = threadIdx.x;
    int w = tid >> 5, lane = tid & 31;
    int g = lane >> 2, t4 = lane & 3;
    int wm = w / WGN, wn = w % WGN;
    int n0 = blockIdx.x * 128, m0 = blockIdx.y * BM;

    float acc[2][NT][4];
#pragma unroll
    for (int mt = 0; mt < 2; mt++)
#pragma unroll
        for (int nt = 0; nt < NT; nt++)
#pragma unroll
            for (int i = 0; i < 4; i++) acc[mt][nt][i] = 0.f;

    // staging maps (float4 granularity, rows of 8 float4 slots)
    constexpr int APT  = BM / 32;        // A float4 slots per thread (4 or 2)
    constexpr int TPRA = 8 / APT;        // threads per A row
    int lrowA = tid / TPRA;
    int baseA = (tid % TPRA) * APT;
    int lrowB = tid >> 1;
    int baseB = (tid & 1) * 4;

    const float* Agp = A  + (size_t)(m0 + lrowA) * K + (baseA << 2);
    const float* Bgp = BT + (size_t)(n0 + lrowB) * K + (baseB << 2);
    uint32_t aS = sbase + (uint32_t)(lrowA * SSTR + baseA * 4) * 4;
    uint32_t bS = sbase + (uint32_t)(2 * AW + lrowB * SSTR + baseB * 4) * 4;

    int nch = K >> 5;

    // prologue: stage chunks 0 (buf0) and 1 (buf1)
#pragma unroll
    for (int s = 0; s < APT; s++) cpa16(aS + s * 16, Agp + s * 4);
#pragma unroll
    for (int s = 0; s < 4; s++)   cpa16(bS + s * 16, Bgp + s * 4);
    CP_COMMIT();
#pragma unroll
    for (int s = 0; s < APT; s++) cpa16(aS + AW * 4 + s * 16, Agp + BKC + s * 4);
#pragma unroll
    for (int s = 0; s < 4; s++)   cpa16(bS + BW * 4 + s * 16, Bgp + BKC + s * 4);
    CP_COMMIT();

    for (int c = 0; c < nch; c++) {
        int buf = c & 1;
        CP_WAIT1();                 // chunk c landed
        __syncthreads();
        const uint32_t* Abuf = smem + buf * AW;
        const uint32_t* Bbuf = smem + 2 * AW + buf * BW;
#pragma unroll
        for (int k8 = 0; k8 < BKC / 8; k8++) {
            int kk = (k8 << 3) + t4;
            uint32_t af[2][4];
#pragma unroll
            for (int mt = 0; mt < 2; mt++) {
                const uint32_t* ap = Abuf + (wm * 32 + mt * 16 + g) * SSTR + kk;
                af[mt][0] = f2tf(__uint_as_float(ap[0]));
                af[mt][1] = f2tf(__uint_as_float(ap[8 * SSTR]));
                af[mt][2] = f2tf(__uint_as_float(ap[4]));
                af[mt][3] = f2tf(__uint_as_float(ap[8 * SSTR + 4]));
            }
            uint32_t bf[NT][2];
#pragma unroll
            for (int nt = 0; nt < NT; nt++) {
                const uint32_t* bp = Bbuf + (wn * (NT * 8) + nt * 8 + g) * SSTR + kk;
                bf[nt][0] = f2tf(__uint_as_float(bp[0]));
                bf[nt][1] = f2tf(__uint_as_float(bp[4]));
            }
#pragma unroll
            for (int mt = 0; mt < 2; mt++)
#pragma unroll
                for (int nt = 0; nt < NT; nt++)
                    mma_tf32(acc[mt][nt], af[mt], bf[nt]);
        }
        __syncthreads();            // all warps done with buf before restage
        if (c + 2 < nch) {
            const float* Ag2 = Agp + (c + 2) * BKC;
            const float* Bg2 = Bgp + (c + 2) * BKC;
            uint32_t a2 = aS + (uint32_t)buf * (AW * 4);
            uint32_t b2 = bS + (uint32_t)buf * (BW * 4);
#pragma unroll
            for (int s = 0; s < APT; s++) cpa16(a2 + s * 16, Ag2 + s * 4);
#pragma unroll
            for (int s = 0; s < 4; s++)   cpa16(b2 + s * 16, Bg2 + s * 4);
        }
        CP_COMMIT();                // commit (possibly empty) to keep counts aligned
    }

    // epilogue: c0,c1 -> (row, col,col+1); c2,c3 -> (row+8, col,col+1)
#pragma unroll
    for (int mt = 0; mt < 2; mt++) {
        int r0 = m0 + wm * 32 + mt * 16 + g;
#pragma unroll
        for (int nt = 0; nt < NT; nt++) {
            int cc = n0 + wn * (NT * 8) + nt * 8 + t4 * 2;
            float2 v0 = make_float2(acc[mt][nt][0], acc[mt][nt][1]);
            float2 v1 = make_float2(acc[mt][nt][2], acc[mt][nt][3]);
            if (BIAS) {
                float2 bb = *(const float2*)(bias + cc);
                v0.x += bb.x; v0.y += bb.y; v1.x += bb.x; v1.y += bb.y;
            }
            if (RELU) {
                v0.x = fmaxf(v0.x, 0.f); v0.y = fmaxf(v0.y, 0.f);
                v1.x = fmaxf(v1.x, 0.f); v1.y = fmaxf(v1.y, 0.f);
            }
            if (RES) {
                float2 r4 = *(const float2*)(res + (size_t)r0 * N + cc);
                v0.x += r4.x; v0.y += r4.y;
                float2 r5 = *(const float2*)(res + (size_t)(r0 + 8) * N + cc);
                v1.x += r5.x; v1.y += r5.y;
            }
            *(float2*)(C + (size_t)r0 * N + cc) = v0;
            *(float2*)(C + (size_t)(r0 + 8) * N + cc) = v1;
        }
    }
}

template <int BM, bool BIAS, bool RELU, bool RES>
static inline void tgemm(const float* A, const float* BT, const float* bias,
                         const float* res, float* C, int M, int N, int K) {
    constexpr int SMB = (2 * BM * SSTR + 2 * 128 * SSTR) * 4;
    cudaFuncSetAttribute(mm_gemm<BM, BIAS, RELU, RES>,
                         cudaFuncAttributeMaxDynamicSharedMemorySize, SMB);
    dim3 grid(N / 128, M / BM);
    mm_gemm<BM, BIAS, RELU, RES><<<grid, 256, SMB>>>(A, BT, bias, res, C, M, N, K);
}

// ---------------------------------------------------------------------------
// Weight transpose: [K,N] row-major -> [N,K] row-major
// ---------------------------------------------------------------------------
struct P8 { const float* p[8]; };

__global__ void trans_dd(P8 s, float* dst) {
    __shared__ float t[32][33];
    int z = blockIdx.z;
    int kd = z / 6, i = z - kd * 6;
    const float* src = s.p[kd] + (size_t)i * 262144;
    float* d = dst + (size_t)i * WBLK_STRIDE + (size_t)kd * 262144;
    int tx = threadIdx.x, ty = threadIdx.y;
    int x = blockIdx.x * 32 + tx;
    int y0 = blockIdx.y * 32;
#pragma unroll
    for (int r = 0; r < 32; r += 8)
        t[ty + r][tx] = src[(size_t)(y0 + ty + r) * 512 + x];
    __syncthreads();
    int x2 = y0 + tx;
    int y2 = blockIdx.x * 32;
#pragma unroll
    for (int r = 0; r < 32; r += 8)
        d[(size_t)(y2 + ty + r) * 512 + x2] = t[tx][ty + r];
}

__global__ void trans_rc(const float* __restrict__ src, float* __restrict__ dst,
                         int R, int C, size_t dOff) {
    __shared__ float t[32][33];
    const float* s = src + (size_t)blockIdx.z * R * C;
    float* d = dst + (size_t)blockIdx.z * WBLK_STRIDE + dOff;
    int tx = threadIdx.x, ty = threadIdx.y;
    int x = blockIdx.x * 32 + tx;
    int y0 = blockIdx.y * 32;
#pragma unroll
    for (int r = 0; r < 32; r += 8)
        t[ty + r][tx] = s[(size_t)(y0 + ty + r) * C + x];
    __syncthreads();
    int x2 = y0 + tx;
    int y2 = blockIdx.x * 32;
#pragma unroll
    for (int r = 0; r < 32; r += 8)
        d[(size_t)(y2 + ty + r) * R + x2] = t[tx][ty + r];
}

// ---------------------------------------------------------------------------
// Embedding * sqrt(D) + sinusoidal positional encoding
// ---------------------------------------------------------------------------
__global__ void embed_kernel(const int* __restrict__ x,
                             const float* __restrict__ emb,
                             float* __restrict__ h) {
    int n = blockIdx.x;
    int l = n & (Ll - 1);
    int tok = x[n];
    int d0 = threadIdx.x * 4;
#pragma unroll
    for (int u = 0; u < 4; u++) {
        int d = d0 + u;
        int i = (d < 256) ? d : d - 256;
        float denom = powf(10000.0f, (float)i * (1.0f / 256.0f));
        float ang = (float)l / denom;
        float pos = (d < 256) ? sinf(ang) : cosf(ang);
        h[(size_t)n * Dm + d] = emb[(size_t)tok * Dm + d] * 22.62741699796952f + pos;
    }
}

// ---------------------------------------------------------------------------
// LayerNorm: one block per row (D=512), 128 threads
// ---------------------------------------------------------------------------
__global__ void ln_kernel(const float* __restrict__ x,
                          const float* __restrict__ gw,
                          const float* __restrict__ bw,
                          float* __restrict__ y) {
    int row = blockIdx.x;
    int t = threadIdx.x;
    float4 xv = ((const float4*)(x + (size_t)row * Dm))[t];
    float s  = xv.x + xv.y + xv.z + xv.w;
    float ss = xv.x * xv.x + xv.y * xv.y + xv.z * xv.z + xv.w * xv.w;
#pragma unroll
    for (int o = 16; o > 0; o >>= 1) {
        s  += __shfl_xor_sync(0xFFFFFFFFu, s, o);
        ss += __shfl_xor_sync(0xFFFFFFFFu, ss, o);
    }
    __shared__ float sh_s[4], sh_ss[4];
    int w = t >> 5, lane = t & 31;
    if (lane == 0) { sh_s[w] = s; sh_ss[w] = ss; }
    __syncthreads();
    s  = sh_s[0] + sh_s[1] + sh_s[2] + sh_s[3];
    ss = sh_ss[0] + sh_ss[1] + sh_ss[2] + sh_ss[3];
    float mean = s * (1.0f / Dm);
    float var  = ss * (1.0f / Dm) - mean * mean;
    float inv = rsqrtf(var + 1e-6f);
    float4 gv = ((const float4*)gw)[t];
    float4 bv = ((const float4*)bw)[t];
    float4 ov;
    ov.x = (xv.x - mean) * inv * gv.x + bv.x;
    ov.y = (xv.y - mean) * inv * gv.y + bv.y;
    ov.z = (xv.z - mean) * inv * gv.z + bv.z;
    ov.w = (xv.w - mean) * inv * gv.w + bv.w;
    ((float4*)(y + (size_t)row * Dm))[t] = ov;
}

// ---------------------------------------------------------------------------
// Fused flash-style attention (fp32)
// ---------------------------------------------------------------------------
template <bool CAUSAL>
__global__ void __launch_bounds__(128)
attn_kernel(const float* __restrict__ Q, const float* __restrict__ K,
            const float* __restrict__ V, float* __restrict__ O) {
    __shared__ float Ks[64][64];
    __shared__ float Vs[64][64];
    int t = threadIdx.x;
    int qt = blockIdx.x, hh = blockIdx.y, b = blockIdx.z;
    int q = qt * 128 + t;
    const float* qptr = Q + ((size_t)(b * Ll + q)) * Dm + hh * DH;
    float4 qv[16];
#pragma unroll
    for (int d = 0; d < 16; d++) qv[d] = ((const float4*)qptr)[d];
    float4 ov[16];
#pragma unroll
    for (int d = 0; d < 16; d++) ov[d] = make_float4(0.f, 0.f, 0.f, 0.f);
    float m = -1e30f, lsum = 0.f;

    int kmax = CAUSAL ? (qt * 128 + 128) : Ll;
    for (int k0 = 0; k0 < kmax; k0 += 64) {
#pragma unroll
        for (int it = 0; it < 8; it++) {
            int idx = t + it * 128;
            int r = idx >> 4;
            int c = (idx & 15) << 2;
            size_t off = ((size_t)(b * Ll + k0 + r)) * Dm + hh * DH + c;
            *(float4*)&Ks[r][c] = *(const float4*)(K + off);
            *(float4*)&Vs[r][c] = *(const float4*)(V + off);
        }
        __syncthreads();
        int jend = 64;
        if (CAUSAL) {
            int lim = q - k0 + 1;
            jend = lim < 64 ? (lim < 0 ? 0 : lim) : 64;
        }
        for (int j = 0; j < jend; j++) {
            const float4* kr = (const float4*)Ks[j];
            float s = 0.f;
#pragma unroll
            for (int d = 0; d < 16; d++) {
                float4 kv = kr[d];
                s += qv[d].x * kv.x + qv[d].y * kv.y + qv[d].z * kv.z + qv[d].w * kv.w;
            }
            s *= 0.125f;
            float mn = fmaxf(m, s);
            float c = __expf(m - mn);
            float p = __expf(s - mn);
            m = mn;
            lsum = lsum * c + p;
            const float4* vr = (const float4*)Vs[j];
#pragma unroll
            for (int d = 0; d < 16; d++) {
                float4 vvv = vr[d];
                ov[d].x = ov[d].x * c + p * vvv.x;
                ov[d].y = ov[d].y * c + p * vvv.y;
                ov[d].z = ov[d].z * c + p * vvv.z;
                ov[d].w = ov[d].w * c + p * vvv.w;
            }
        }
        __syncthreads();
    }
    float inv = 1.0f / lsum;
    float* optr = O + ((size_t)(b * Ll + q)) * Dm + hh * DH;
#pragma unroll
    for (int d = 0; d < 16; d++) {
        float4 r = ov[d];
        r.x *= inv; r.y *= inv; r.z *= inv; r.w *= inv;
        ((float4*)optr)[d] = r;
    }
}

// ---------------------------------------------------------------------------
// kernel_launch
// ---------------------------------------------------------------------------
extern "C" void kernel_launch(void* const* d_in, const int* in_sizes, int n_in,
                              void* d_out, int out_size) {
    const int*   x     = (const int*)  d_in[0];
    const float* ctx   = (const float*)d_in[1];
    const float* emb   = (const float*)d_in[2];
    const float* wq_s  = (const float*)d_in[3];
    const float* wk_s  = (const float*)d_in[4];
    const float* wv_s  = (const float*)d_in[5];
    const float* wo_s  = (const float*)d_in[6];
    const float* wq_c  = (const float*)d_in[7];
    const float* wk_c  = (const float*)d_in[8];
    const float* wv_c  = (const float*)d_in[9];
    const float* wo_c  = (const float*)d_in[10];
    const float* w1    = (const float*)d_in[11];
    const float* b1    = (const float*)d_in[12];
    const float* w2    = (const float*)d_in[13];
    const float* b2    = (const float*)d_in[14];
    const float* ln1_g = (const float*)d_in[15];
    const float* ln1_b = (const float*)d_in[16];
    const float* ln2_g = (const float*)d_in[17];
    const float* ln2_b = (const float*)d_in[18];
    const float* ln3_g = (const float*)d_in[19];
    const float* ln3_b = (const float*)d_in[20];
    const float* lnf_g = (const float*)d_in[21];
    const float* lnf_b = (const float*)d_in[22];
    float* out = (float*)d_out;

    float *h, *y, *q, *k, *v, *o, *ff, *wt;
    cudaGetSymbolAddress((void**)&h,  g_h);
    cudaGetSymbolAddress((void**)&y,  g_y);
    cudaGetSymbolAddress((void**)&q,  g_q);
    cudaGetSymbolAddress((void**)&k,  g_k);
    cudaGetSymbolAddress((void**)&v,  g_v);
    cudaGetSymbolAddress((void**)&o,  g_o);
    cudaGetSymbolAddress((void**)&ff, g_ff);
    cudaGetSymbolAddress((void**)&wt, g_wt);

    // ---- transpose all weights into [N][K] scratch ----
    P8 p8;
    p8.p[0] = wq_s; p8.p[1] = wk_s; p8.p[2] = wv_s; p8.p[3] = wo_s;
    p8.p[4] = wq_c; p8.p[5] = wk_c; p8.p[6] = wv_c; p8.p[7] = wo_c;
    trans_dd<<<dim3(16, 16, 48), dim3(32, 8)>>>(p8, wt);
    trans_rc<<<dim3(64, 16, 6), dim3(32, 8)>>>(w1, wt, 512, 2048, W1T_OFF);
    trans_rc<<<dim3(16, 64, 6), dim3(32, 8)>>>(w2, wt, 2048, 512, W2T_OFF);

    embed_kernel<<<NTOK, 128>>>(x, emb, h);

    dim3 agrid(Ll / 128, Hn, Bb);

    for (int i = 0; i < NBLK; i++) {
        const float* WT = wt + (size_t)i * WBLK_STRIDE;
        // --- self attention ---  (N=512 GEMMs use BM=64 -> 128 CTAs)
        ln_kernel<<<NTOK, 128>>>(h, ln1_g + i * Dm, ln1_b + i * Dm, y);
        tgemm<64, false, false, false>(y, WT + 0 * 262144ull, nullptr, nullptr, q, NTOK, Dm, Dm);
        tgemm<64, false, false, false>(y, WT + 1 * 262144ull, nullptr, nullptr, k, NTOK, Dm, Dm);
        tgemm<64, false, false, false>(y, WT + 2 * 262144ull, nullptr, nullptr, v, NTOK, Dm, Dm);
        attn_kernel<true><<<agrid, 128>>>(q, k, v, o);
        tgemm<64, false, false, true>(o, WT + 3 * 262144ull, nullptr, h, h, NTOK, Dm, Dm);

        // --- cross attention ---
        ln_kernel<<<NTOK, 128>>>(h, ln2_g + i * Dm, ln2_b + i * Dm, y);
        tgemm<64, false, false, false>(y,   WT + 4 * 262144ull, nullptr, nullptr, q, NTOK, Dm, Dm);
        tgemm<64, false, false, false>(ctx, WT + 5 * 262144ull, nullptr, nullptr, k, NTOK, Dm, Dm);
        tgemm<64, false, false, false>(ctx, WT + 6 * 262144ull, nullptr, nullptr, v, NTOK, Dm, Dm);
        attn_kernel<false><<<agrid, 128>>>(q, k, v, o);
        tgemm<64, false, false, true>(o, WT + 7 * 262144ull, nullptr, h, h, NTOK, Dm, Dm);

        // --- FFN ---
        ln_kernel<<<NTOK, 128>>>(h, ln3_g + i * Dm, ln3_b + i * Dm, y);
        tgemm<128, true, true, false>(y,  WT + W1T_OFF, b1 + (size_t)i * Ff, nullptr, ff, NTOK, Ff, Dm);
        tgemm<64, true, false, true>(ff, WT + W2T_OFF, b2 + (size_t)i * Dm, h, h, NTOK, Dm, Ff);
    }

    // --- final LN + logits = y @ emb^T (emb already [V][K]) ---
    ln_kernel<<<NTOK, 128>>>(h, lnf_g, lnf_b, y);
    tgemm<128, false, false, false>(y, emb, nullptr, nullptr, out, NTOK, Vv, Dm);
}